// round 7
// baseline (speedup 1.0000x reference)
#include <cuda_runtime.h>
#include <cstdint>

// ============================================================================
// relu(x @ W^T + b):  B=131072, D_IN=D_OUT=256, fp32 in/out.
//
// mma.sync m16n8k8 tf32, cvt.rna operands (unbiased -> rel_err ~2.8e-4).
//
// R7 change vs R6 (122.9us, L1TEX-bound at 65%): 8 fat warps instead of 16.
// Warp tile 64x64 (128 acc regs/thread, 256 threads) halves the A-fragment
// shared-read amplification (x8 -> x4): LDS read volume 192KB -> 128KB/chunk.
// Pitch-36 padded SMEM (conflict-free scalar LDS, aligned float4 STS),
// 2-stage double buffer + one-chunk-ahead register prefetch, kept verbatim.
// ============================================================================

#define DEVINL static __device__ __forceinline__

static constexpr int DIM     = 256;
static constexpr int TILE_M  = 128;
static constexpr int NCH     = 8;                  // K chunks of 32
static constexpr int PITCH   = 36;                 // padded floats per row-chunk
static constexpr int THREADS = 256;

static constexpr int A_WORDS     = TILE_M * PITCH;        // 4608
static constexpr int B_WORDS     = DIM * PITCH;           // 9216
static constexpr int STAGE_WORDS = A_WORDS + B_WORDS;     // 13824
static constexpr int BIAS_WORDS  = 256;
static constexpr int SMEM_BYTES  = (BIAS_WORDS + 2 * STAGE_WORDS) * 4; // 111616

DEVINL uint32_t f2tf(float f) {
    uint32_t r;
    asm("cvt.rna.tf32.f32 %0, %1;" : "=r"(r) : "f"(f));
    return r;
}

DEVINL void mma_tf32(float* d, const uint32_t* a, const uint32_t* b) {
    asm volatile(
        "mma.sync.aligned.m16n8k8.row.col.f32.tf32.tf32.f32 "
        "{%0,%1,%2,%3}, {%4,%5,%6,%7}, {%8,%9}, {%0,%1,%2,%3};"
        : "+f"(d[0]), "+f"(d[1]), "+f"(d[2]), "+f"(d[3])
        : "r"(a[0]), "r"(a[1]), "r"(a[2]), "r"(a[3]),
          "r"(b[0]), "r"(b[1]));
}

__global__ void __launch_bounds__(THREADS, 1)
gemm_bias_relu_mma(const float4* __restrict__ x4,
                   const float4* __restrict__ w4,
                   const float*  __restrict__ bias,
                   float2*       __restrict__ out2) {
    extern __shared__ uint32_t sm[];
    float*    bsm  = (float*)sm;
    uint32_t* stg0 = sm + BIAS_WORDS;
    uint32_t* stg1 = sm + BIAS_WORDS + STAGE_WORDS;

    const int  tid    = threadIdx.x;
    const long m_base = (long)blockIdx.x * TILE_M;

    bsm[tid] = bias[tid];

    // ---------------- loader mapping (256 threads) ----------------
    // Thread owns A rows {lr+32i, i=0..3} and B rows {lr+32j, j=0..7},
    // float4 group kg within the 32-wide K chunk. 12 float4 per chunk.
    const int lr = tid >> 3;   // 0..31
    const int kg = tid & 7;    // 0..7

    long ga[4], gb[8];
    int  sa[4], sb[8];
#pragma unroll
    for (int i = 0; i < 4; i++) {
        ga[i] = (m_base + lr + 32 * i) * 64 + kg;        // x pitch = 64 float4
        sa[i] = (lr + 32 * i) * PITCH + kg * 4;
    }
#pragma unroll
    for (int j = 0; j < 8; j++) {
        gb[j] = (long)(lr + 32 * j) * 64 + kg;           // W pitch = 64 float4
        sb[j] = A_WORDS + (lr + 32 * j) * PITCH + kg * 4;
    }

    float4 ra[4], rb[8];

    auto ldg_chunk = [&](int c) {
        const long o = (long)c * 8;
#pragma unroll
        for (int i = 0; i < 4; i++) ra[i] = x4[ga[i] + o];
#pragma unroll
        for (int j = 0; j < 8; j++) rb[j] = w4[gb[j] + o];
    };

    auto cvt4 = [](float4 v) {
        uint4 u;
        u.x = f2tf(v.x); u.y = f2tf(v.y); u.z = f2tf(v.z); u.w = f2tf(v.w);
        return u;
    };

    auto sts_chunk = [&](uint32_t* s) {
#pragma unroll
        for (int i = 0; i < 4; i++) *(uint4*)(s + sa[i]) = cvt4(ra[i]);
#pragma unroll
        for (int j = 0; j < 8; j++) *(uint4*)(s + sb[j]) = cvt4(rb[j]);
    };

    // ---------------- compute mapping ----------------
    // 8 warps in a 2(M) x 4(N) grid: warp tile 64x64.
    const int wid = tid >> 5, l = tid & 31;
    const int mw = wid >> 2, nw = wid & 3;
    const int qr = l >> 2, ql = l & 3;

    int aoff[4], boff[8];
#pragma unroll
    for (int mi = 0; mi < 4; mi++)
        aoff[mi] = (mw * 64 + mi * 16 + qr) * PITCH + ql;
#pragma unroll
    for (int ni = 0; ni < 8; ni++)
        boff[ni] = A_WORDS + (nw * 64 + ni * 8 + qr) * PITCH + ql;

    float acc[4][8][4];
#pragma unroll
    for (int mi = 0; mi < 4; mi++)
#pragma unroll
        for (int ni = 0; ni < 8; ni++)
#pragma unroll
            for (int r = 0; r < 4; r++) acc[mi][ni][r] = 0.0f;

    auto compute_chunk = [&](const uint32_t* s) {
#pragma unroll
        for (int ks = 0; ks < 4; ks++) {
            uint32_t a[4][4], b[8][2];
#pragma unroll
            for (int mi = 0; mi < 4; mi++) {
                const int ba = aoff[mi] + ks * 8;
                a[mi][0] = s[ba];
                a[mi][1] = s[ba + 8 * PITCH];
                a[mi][2] = s[ba + 4];
                a[mi][3] = s[ba + 8 * PITCH + 4];
            }
#pragma unroll
            for (int ni = 0; ni < 8; ni++) {
                const int bb = boff[ni] + ks * 8;
                b[ni][0] = s[bb];
                b[ni][1] = s[bb + 4];
            }
#pragma unroll
            for (int mi = 0; mi < 4; mi++)
#pragma unroll
                for (int ni = 0; ni < 8; ni++)
                    mma_tf32(acc[mi][ni], a[mi], b[ni]);
        }
    };

    // ---------------- pipeline ----------------
    ldg_chunk(0);
    sts_chunk(stg0);
    ldg_chunk(1);
    __syncthreads();

    uint32_t* cur = stg0;
    uint32_t* nxt = stg1;
#pragma unroll 1
    for (int c = 0; c < NCH; c++) {
        compute_chunk(cur);
        if (c < NCH - 1) {
            sts_chunk(nxt);                    // regs hold chunk c+1
            if (c < NCH - 2) ldg_chunk(c + 2); // latency hidden by compute(c+1)
        }
        __syncthreads();
        uint32_t* t = cur; cur = nxt; nxt = t;
    }

    // ---------------- epilogue: bias + relu, float2 stores ----------------
#pragma unroll
    for (int mi = 0; mi < 4; mi++) {
        const long r0 = m_base + mw * 64 + mi * 16 + qr;
#pragma unroll
        for (int ni = 0; ni < 8; ni++) {
            const int col = nw * 64 + ni * 8 + ql * 2;
            const float b0 = bsm[col], b1 = bsm[col + 1];
            float2 v0, v1;
            v0.x = fmaxf(acc[mi][ni][0] + b0, 0.0f);
            v0.y = fmaxf(acc[mi][ni][1] + b1, 0.0f);
            v1.x = fmaxf(acc[mi][ni][2] + b0, 0.0f);
            v1.y = fmaxf(acc[mi][ni][3] + b1, 0.0f);
            out2[r0 * 128 + (col >> 1)]       = v0;
            out2[(r0 + 8) * 128 + (col >> 1)] = v1;
        }
    }
}

extern "C" void kernel_launch(void* const* d_in, const int* in_sizes, int n_in,
                              void* d_out, int out_size) {
    const float* x = (const float*)d_in[0];   // [B, 256]
    const float* W = (const float*)d_in[1];   // [256, 256]
    const float* b = (const float*)d_in[2];   // [256]

    const int rows = in_sizes[0] / DIM;       // 131072
    const int grid = rows / TILE_M;           // 1024

    cudaFuncSetAttribute(gemm_bias_relu_mma,
                         cudaFuncAttributeMaxDynamicSharedMemorySize, SMEM_BYTES);
    gemm_bias_relu_mma<<<grid, THREADS, SMEM_BYTES>>>(
        (const float4*)x, (const float4*)W, b, (float2*)d_out);
}